// round 1
// baseline (speedup 1.0000x reference)
#include <cuda_runtime.h>
#include <math.h>

// Problem constants (fixed by the dataset: B=16, H=W=8, CIN=COUT=32)
#define CI 32
#define CO 32
#define CH 18
#define NB 16
#define NSPAT 64          // H*W
#define NTOT 1024         // NB * NSPAT
#define EPSV 1e-9f
#define LN10 2.3025850929940457f

// Per-position routing results (scratch; __device__ globals to satisfy the
// no-allocation rule). Reduced over the spatial grid by reduce_kernel.
__device__ float g_act[NTOT * CO];            // act_out per (n, c)
__device__ float g_miu[NTOT * CO * CH];       // miu per (n, c, ch)

__device__ __forceinline__ float warp_sum(float v) {
#pragma unroll
    for (int o = 16; o; o >>= 1) v += __shfl_xor_sync(0xffffffffu, v, o);
    return v;
}

// One CTA per spatial position n. 32 warps: warp = output capsule c,
// lane = input capsule i. Each thread owns votes[n, i, c, 0..17] in registers.
__global__ void __launch_bounds__(1024, 1)
caps_kernel(const float* __restrict__ x,
            const float* __restrict__ w,
            const float* __restrict__ beta_v,
            const float* __restrict__ beta_a,
            const float* __restrict__ coord)
{
    __shared__ float xs[CI * 17];        // this position's x row (pose+act)
    __shared__ float buf[32 * 33];       // cross-warp (per-i) reduce buffer, padded
    __shared__ float miu_s[CO][CH];      // current miu per (c, ch)
    __shared__ float hls_s[CO][CH];      // 0.5 * log(sigma_sq)
    __shared__ float i2s_s[CO][CH];      // 0.5 / sigma_sq
    __shared__ float rs_s[CO];           // softmax logits per c

    const int n   = blockIdx.x;
    const int tid = threadIdx.x;
    const int c   = tid >> 5;            // warp id = output capsule
    const int i   = tid & 31;            // lane    = input capsule

    if (tid < CI * 17) xs[tid] = x[n * (CI * 17) + tid];
    __syncthreads();

    // --- votes: pose_i (4x4) @ w[i][c] (4x4), plus 2 coord channels ---
    // w layout: [ci][co][4][4]; rows b as float4 (contiguous d).
    const float4* wv = reinterpret_cast<const float4*>(w) + (i * CO + c) * 4;
    const float4 w0 = wv[0], w1 = wv[1], w2 = wv[2], w3 = wv[3];

    float v[CH];
    {
        const int s = n & (NSPAT - 1);
        v[0] = coord[2 * s + 0];
        v[1] = coord[2 * s + 1];
        const float* pr = &xs[i * 17];   // lane-strided by 17: bank-conflict free
#pragma unroll
        for (int a = 0; a < 4; a++) {
            const float p0 = pr[a * 4 + 0], p1 = pr[a * 4 + 1];
            const float p2 = pr[a * 4 + 2], p3 = pr[a * 4 + 3];
            v[2 + a * 4 + 0] = p0 * w0.x + p1 * w1.x + p2 * w2.x + p3 * w3.x;
            v[2 + a * 4 + 1] = p0 * w0.y + p1 * w1.y + p2 * w2.y + p3 * w3.y;
            v[2 + a * 4 + 2] = p0 * w0.z + p1 * w1.z + p2 * w2.z + p3 * w3.z;
            v[2 + a * 4 + 3] = p0 * w0.w + p1 * w1.w + p2 * w2.w + p3 * w3.w;
        }
    }
    const float act_in = xs[i * 17 + 16];

    float r  = 1.0f / CO;     // routing coefficient r[i][c]
    float ao = 0.0f;          // act_out[c] (valid after iteration 0)

    for (int it = 0; it < 3; it++) {
        if (it > 0) {
            // ---- E-step ----
            float S = 0.0f, m = -1e30f;
#pragma unroll
            for (int ch = 0; ch < CH; ch++) {
                const float d  = v[ch] - miu_s[c][ch];
                const float lp = fmaf(-d * d, i2s_s[c][ch], -hls_s[c][ch]);
                S += lp;
                m = fmaxf(m, lp);
            }
            __syncthreads();                       // WAR guard on buf
            buf[c * 33 + i] = m;
            __syncthreads();
            float M = -1e30f;                      // max over (c, ch) for this i
#pragma unroll
            for (int cc = 0; cc < CO; cc++) M = fmaxf(M, buf[cc * 33 + i]);
            const float pv = __expf(S - (float)CH * (M - LN10));
            const float ap = pv * ao;
            __syncthreads();
            buf[c * 33 + i] = ap;
            __syncthreads();
            float sum_ap = 0.0f;
#pragma unroll
            for (int cc = 0; cc < CO; cc++) sum_ap += buf[cc * 33 + i];
            r = ap / (sum_ap + EPSV);
        }

        // ---- M-step ----
        r *= act_in;
        __syncthreads();
        buf[c * 33 + i] = r;
        __syncthreads();
        float sc = 0.0f;                           // sum over c for this i
#pragma unroll
        for (int cc = 0; cc < CO; cc++) sc += buf[cc * 33 + i];
        r /= (sc + EPSV);

        const float r_sum = warp_sum(r);           // sum over i (all lanes hold it)
        const float r1 = r / (r_sum + EPSV);

        float bsum = 0.0f;
#pragma unroll
        for (int ch = 0; ch < CH; ch++) {
            const float mu = warp_sum(v[ch] * r1);
            const float d  = v[ch] - mu;
            const float sg = warp_sum(d * d * r1) + EPSV;
            const float hl = 0.5f * __logf(sg);
            if (i == 0) {
                miu_s[c][ch] = mu;
                hls_s[c][ch] = hl;
                i2s_s[c][ch] = 0.5f / sg;
            }
            if (it == 2) bsum += beta_v[c * CH + ch] + hl;
        }

        // ---- activation update (softmax over c) ----
        const float logit = (it == 2) ? 0.03f * (beta_a[c] - bsum * r_sum)
                                      : r_sum;
        __syncthreads();                           // also publishes miu/hls/i2s
        if (i == 0) rs_s[c] = logit;
        __syncthreads();
        float mx = -1e30f;
#pragma unroll
        for (int cc = 0; cc < CO; cc++) mx = fmaxf(mx, rs_s[cc]);
        float se = 0.0f;
#pragma unroll
        for (int cc = 0; cc < CO; cc++) se += __expf(rs_s[cc] - mx);
        ao = __expf(logit - mx) / se;
    }

    // ---- write per-position results ----
    if (i == 0)  g_act[n * CO + c] = ao;
    if (i < CH)  g_miu[(n * CO + c) * CH + i] = miu_s[c][i];
}

// Deterministic spatial mean: out = [outputs (16*32) | pose_out (16*32*18)]
__global__ void reduce_kernel(float* __restrict__ out)
{
    const int NA = NB * CO;            // 512
    const int NP = NB * CO * CH;       // 9216
    const int idx = blockIdx.x * blockDim.x + threadIdx.x;
    if (idx < NA) {
        const int b = idx / CO, cc = idx % CO;
        float s = 0.0f;
        for (int sp = 0; sp < NSPAT; sp++) s += g_act[(b * NSPAT + sp) * CO + cc];
        out[idx] = s * (1.0f / NSPAT);
    } else if (idx < NA + NP) {
        const int j = idx - NA;
        const int b = j / (CO * CH), rem = j % (CO * CH);
        float s = 0.0f;
        for (int sp = 0; sp < NSPAT; sp++) s += g_miu[(b * NSPAT + sp) * (CO * CH) + rem];
        out[idx] = s * (1.0f / NSPAT);
    }
}

extern "C" void kernel_launch(void* const* d_in, const int* in_sizes, int n_in,
                              void* d_out, int out_size)
{
    const float* x      = (const float*)d_in[0];
    const float* w      = (const float*)d_in[1];
    const float* beta_v = (const float*)d_in[2];
    const float* beta_a = (const float*)d_in[3];
    const float* coord  = (const float*)d_in[4];
    float* out = (float*)d_out;

    caps_kernel<<<NTOT, 1024>>>(x, w, beta_v, beta_a, coord);

    const int total = NB * CO + NB * CO * CH;   // 9728
    reduce_kernel<<<(total + 255) / 256, 256>>>(out);
}

// round 3
// speedup vs baseline: 1.4328x; 1.4328x over previous
#include <cuda_runtime.h>
#include <math.h>

// Problem constants (fixed by the dataset: B=16, H=W=8, CIN=COUT=32)
#define CI 32
#define CO 32
#define CH 18
#define NB 16
#define NSPAT 64          // H*W
#define NTOT 1024         // NB * NSPAT
#define EPSV 1e-9f
#define LN10 2.3025850929940457f

// Per-position routing results (scratch; __device__ globals per no-alloc rule)
__device__ float g_act[NTOT * CO];            // act_out per (n, c)
__device__ float g_miu[NTOT * CO * CH];       // miu per (n, c, ch)

// NOTE: redux.sync.f32 is NOT in sm_103's ISA (ptxas rejects it) — butterfly SHFLs.
__device__ __forceinline__ float warp_sum(float v) {
#pragma unroll
    for (int o = 16; o; o >>= 1) v += __shfl_xor_sync(0xffffffffu, v, o);
    return v;
}
__device__ __forceinline__ float warp_max(float v) {
#pragma unroll
    for (int o = 16; o; o >>= 1) v = fmaxf(v, __shfl_xor_sync(0xffffffffu, v, o));
    return v;
}

// One CTA per spatial position n. 32 warps: warp = output capsule c,
// lane = input capsule i. Each thread owns votes[n, i, c, 0..17] in registers.
//
// Cross-warp (per-i, over c) reductions use a designated-warp scheme:
//   all threads write buf[c*33+i]; barrier;
//   warp w reads buf[lane*33 + w] (value of pair (c=lane, i=w)), warp-reduces,
//   lane 0 writes col[w]; barrier; every thread reads col[i].
__global__ void __launch_bounds__(1024, 1)
caps_kernel(const float* __restrict__ x,
            const float* __restrict__ w,
            const float* __restrict__ beta_v,
            const float* __restrict__ beta_a,
            const float* __restrict__ coord)
{
    __shared__ float xs[CI * 17];        // this position's x row (pose+act)
    __shared__ float buf[32 * 33];       // cross-warp exchange, padded
    __shared__ float col[32];            // per-i reduction results
    __shared__ float miu_s[CO][CH];      // current miu per (c, ch)
    __shared__ float hls_s[CO][CH];      // 0.5 * log(sigma_sq)
    __shared__ float i2s_s[CO][CH];      // 0.5 / sigma_sq
    __shared__ float rs_s[CO];           // softmax logits -> probs per c

    const int n   = blockIdx.x;
    const int tid = threadIdx.x;
    const int c   = tid >> 5;            // warp id = output capsule
    const int i   = tid & 31;            // lane    = input capsule

    if (tid < CI * 17) xs[tid] = x[n * (CI * 17) + tid];
    __syncthreads();

    // --- votes: pose_i (4x4) @ w[i][c] (4x4), plus 2 coord channels ---
    float v[CH];
    {
        const float4* wv = reinterpret_cast<const float4*>(w) + (i * CO + c) * 4;
        const float4 w0 = wv[0], w1 = wv[1], w2 = wv[2], w3 = wv[3];
        const int s = n & (NSPAT - 1);
        v[0] = coord[2 * s + 0];
        v[1] = coord[2 * s + 1];
        const float* pr = &xs[i * 17];
#pragma unroll
        for (int a = 0; a < 4; a++) {
            const float p0 = pr[a * 4 + 0], p1 = pr[a * 4 + 1];
            const float p2 = pr[a * 4 + 2], p3 = pr[a * 4 + 3];
            v[2 + a * 4 + 0] = p0 * w0.x + p1 * w1.x + p2 * w2.x + p3 * w3.x;
            v[2 + a * 4 + 1] = p0 * w0.y + p1 * w1.y + p2 * w2.y + p3 * w3.y;
            v[2 + a * 4 + 2] = p0 * w0.z + p1 * w1.z + p2 * w2.z + p3 * w3.z;
            v[2 + a * 4 + 3] = p0 * w0.w + p1 * w1.w + p2 * w2.w + p3 * w3.w;
        }
    }
    const float act_in = xs[i * 17 + 16];

    float r  = 1.0f / CO;     // routing coefficient r[i][c]
    float ao = 0.0f;          // act_out[c] (valid after iteration 0)

#pragma unroll
    for (int it = 0; it < 3; it++) {
        if (it > 0) {
            // ---- E-step ----
            float S = 0.0f, m = -1e30f;
#pragma unroll
            for (int ch = 0; ch < CH; ch++) {
                const float d  = v[ch] - miu_s[c][ch];
                const float lp = fmaf(-d * d, i2s_s[c][ch], -hls_s[c][ch]);
                S += lp;
                m = fmaxf(m, lp);
            }
            // pass A: M_i = max over c of m
            buf[c * 33 + i] = m;
            __syncthreads();
            {
                const float t = warp_max(buf[i * 33 + c]);
                if (i == 0) col[c] = t;
            }
            __syncthreads();
            const float M  = col[i];
            const float pv = __expf(S - (float)CH * (M - LN10));
            const float ap = pv * ao;
            // pass B: sum over c of ap
            buf[c * 33 + i] = ap;
            __syncthreads();
            {
                const float t = warp_sum(buf[i * 33 + c]);
                if (i == 0) col[c] = t;
            }
            __syncthreads();
            r = ap / (col[i] + EPSV);
        }

        // ---- M-step ----
        // pass C: sum over c of r*act_in
        const float rv = r * act_in;
        buf[c * 33 + i] = rv;
        __syncthreads();
        {
            const float t = warp_sum(buf[i * 33 + c]);
            if (i == 0) col[c] = t;
        }
        __syncthreads();
        const float rn    = rv / (col[i] + EPSV);
        const float r_sum = warp_sum(rn);            // sum over i
        const float r1    = rn / (r_sum + EPSV);

        float bsum = 0.0f;
#pragma unroll
        for (int ch = 0; ch < CH; ch++) {
            const float mu = warp_sum(v[ch] * r1);
            const float d  = v[ch] - mu;
            const float sg = warp_sum(d * d * r1) + EPSV;
            if (i == 0) {                            // lane 0 is sole consumer
                miu_s[c][ch] = mu;
                const float hl = 0.5f * __logf(sg);
                hls_s[c][ch] = hl;
                i2s_s[c][ch] = __fdividef(0.5f, sg);
                if (it == 2) bsum += beta_v[c * CH + ch] + hl;
            }
        }

        // ---- activation update: softmax over c, computed once by warp 0 ----
        if (i == 0) {
            rs_s[c] = (it == 2) ? 0.03f * (beta_a[c] - bsum * r_sum) : r_sum;
        }
        __syncthreads();                             // also publishes miu/hls/i2s
        if (c == 0) {
            const float t  = rs_s[i];
            const float mx = warp_max(t);
            const float e  = __expf(t - mx);
            const float se = warp_sum(e);
            rs_s[i] = e / se;                        // store normalized probs
        }
        __syncthreads();
        ao = rs_s[c];
    }

    // ---- write per-position results ----
    if (i == 0)  g_act[n * CO + c] = ao;
    if (i < CH)  g_miu[(n * CO + c) * CH + i] = miu_s[c][i];
}

// Deterministic spatial mean: out = [outputs (16*32) | pose_out (16*32*18)]
__global__ void reduce_kernel(float* __restrict__ out)
{
    const int NA = NB * CO;            // 512
    const int NP = NB * CO * CH;       // 9216
    const int idx = blockIdx.x * blockDim.x + threadIdx.x;
    if (idx < NA) {
        const int b = idx / CO, cc = idx % CO;
        float s = 0.0f;
#pragma unroll 8
        for (int sp = 0; sp < NSPAT; sp++) s += g_act[(b * NSPAT + sp) * CO + cc];
        out[idx] = s * (1.0f / NSPAT);
    } else if (idx < NA + NP) {
        const int j = idx - NA;
        const int b = j / (CO * CH), rem = j % (CO * CH);
        float s = 0.0f;
#pragma unroll 8
        for (int sp = 0; sp < NSPAT; sp++) s += g_miu[(b * NSPAT + sp) * (CO * CH) + rem];
        out[idx] = s * (1.0f / NSPAT);
    }
}

extern "C" void kernel_launch(void* const* d_in, const int* in_sizes, int n_in,
                              void* d_out, int out_size)
{
    const float* x      = (const float*)d_in[0];
    const float* w      = (const float*)d_in[1];
    const float* beta_v = (const float*)d_in[2];
    const float* beta_a = (const float*)d_in[3];
    const float* coord  = (const float*)d_in[4];
    float* out = (float*)d_out;

    caps_kernel<<<NTOT, 1024>>>(x, w, beta_v, beta_a, coord);

    const int total = NB * CO + NB * CO * CH;   // 9728
    reduce_kernel<<<(total + 255) / 256, 256>>>(out);
}

// round 4
// speedup vs baseline: 2.3669x; 1.6519x over previous
#include <cuda_runtime.h>
#include <math.h>

// Problem constants (fixed by the dataset: B=16, H=W=8, CIN=COUT=32)
#define CI 32
#define CO 32
#define CH 18
#define CHV 16            // vote channels stored in SMEM (coords handled closed-form)
#define NB 16
#define NSPAT 64          // H*W
#define NTOT 1024         // NB * NSPAT
#define EPSV 1e-9f
#define LN10 2.3025850929940457f

__device__ float g_act[NTOT * CO];            // act_out per (n, c)
__device__ float g_miu[NTOT * CO * CH];       // miu per (n, c, ch)

__device__ __forceinline__ float warp_sum(float v) {
#pragma unroll
    for (int o = 16; o; o >>= 1) v += __shfl_xor_sync(0xffffffffu, v, o);
    return v;
}
__device__ __forceinline__ float warp_max(float v) {
#pragma unroll
    for (int o = 16; o; o >>= 1) v = fmaxf(v, __shfl_xor_sync(0xffffffffu, v, o));
    return v;
}

// Dynamic-SMEM layout (163 KB -> needs opt-in past the 48 KB static limit)
struct SM {
    float vs[2][CHV][CI * CO];   // votes, [p][ch-2][i*32+c]
    float rs[2][CI * CO];        // normalized routing rv, [p][i*32+c]
    float pa[2][CH][CO];         // lp = pa + v*(pb + pg*v)
    float pb[2][CH][CO];
    float pg[2][CH][CO];
    float mu[2][CH][CO];
    float cost[2][CH][CO];
    float xs[2][CI * 17];        // raw x rows (pose+act)
    float logit[2][CO];
    float ao[2][CO];
};

// One CTA = TWO spatial positions (2*blockIdx.x + p). 1024 threads.
// E-step layout: warp = input capsule i, lane = output capsule c.
// M-step layout: warp = channel ch (18 active warps), lane = c; serial i-loop
// in registers — no shuffles.
__global__ void __launch_bounds__(1024, 1)
caps_kernel(const float* __restrict__ x,
            const float* __restrict__ w,
            const float* __restrict__ beta_v,
            const float* __restrict__ beta_a,
            const float* __restrict__ coord)
{
    extern __shared__ float smem_raw[];
    SM* sm = reinterpret_cast<SM*>(smem_raw);

    const int tid = threadIdx.x;
    const int c   = tid & 31;
    const int iw  = tid >> 5;            // E-step: warp id = input capsule i
    const int n0  = blockIdx.x * 2;

    // load both x rows
    for (int k = tid; k < 2 * CI * 17; k += 1024) {
        const int p = (k >= CI * 17);
        sm->xs[p][k - p * CI * 17] = x[(n0 + p) * (CI * 17) + (k - p * CI * 17)];
    }
    __syncthreads();

    // --- votes: pose (4x4) @ w[i][c] (4x4); w loaded once, reused for both p ---
    float v[2][CHV];
    {
        const float4* wv = reinterpret_cast<const float4*>(w) + (iw * CO + c) * 4;
        const float4 w0 = wv[0], w1 = wv[1], w2 = wv[2], w3 = wv[3];
#pragma unroll
        for (int p = 0; p < 2; p++) {
            const float* pr = &sm->xs[p][iw * 17];
#pragma unroll
            for (int a = 0; a < 4; a++) {
                const float p0 = pr[a * 4 + 0], p1 = pr[a * 4 + 1];
                const float p2 = pr[a * 4 + 2], p3 = pr[a * 4 + 3];
                v[p][a * 4 + 0] = p0 * w0.x + p1 * w1.x + p2 * w2.x + p3 * w3.x;
                v[p][a * 4 + 1] = p0 * w0.y + p1 * w1.y + p2 * w2.y + p3 * w3.y;
                v[p][a * 4 + 2] = p0 * w0.z + p1 * w1.z + p2 * w2.z + p3 * w3.z;
                v[p][a * 4 + 3] = p0 * w0.w + p1 * w1.w + p2 * w2.w + p3 * w3.w;
            }
#pragma unroll
            for (int k = 0; k < CHV; k++) sm->vs[p][k][iw * 32 + c] = v[p][k];
        }
    }
    const float act_in[2] = { sm->xs[0][iw * 17 + 16], sm->xs[1][iw * 17 + 16] };
    const int s0 = n0 & (NSPAT - 1);
    const float cx[2] = { coord[2 * s0],     coord[2 * s0 + 2] };
    const float cy[2] = { coord[2 * s0 + 1], coord[2 * s0 + 3] };

    float rr[2] = { 1.0f / CO, 1.0f / CO };
    float ao[2] = { 0.0f, 0.0f };

    for (int it = 0; it < 3; it++) {
        // ---- E-step (warp = i, lane = c) ----
        if (it > 0) {
#pragma unroll
            for (int p = 0; p < 2; p++) {
                float S = 0.0f, m = -1e30f;
#pragma unroll
                for (int ch = 0; ch < CH; ch++) {
                    const float vv = (ch == 0) ? cx[p] : (ch == 1) ? cy[p] : v[p][ch - 2];
                    const float lp = fmaf(fmaf(sm->pg[p][ch][c], vv, sm->pb[p][ch][c]),
                                          vv, sm->pa[p][ch][c]);
                    S += lp;
                    m = fmaxf(m, lp);
                }
                const float M  = warp_max(m);                   // max over (c,ch) for this i
                const float pv = __expf(S - 18.0f * M + 18.0f * LN10);
                const float ap = pv * ao[p];
                const float ss = warp_sum(ap);
                rr[p] = ap / (ss + EPSV);
            }
        }
        // r *= act; normalize over c; publish
#pragma unroll
        for (int p = 0; p < 2; p++) {
            const float rv = rr[p] * act_in[p];
            const float s2 = warp_sum(rv);
            sm->rs[p][iw * 32 + c] = rv / (s2 + EPSV);
        }
        __syncthreads();

        // ---- M-step (warp = ch, lane = c; threads 0..575) ----
        if (tid < CH * 32) {
            const int ch = tid >> 5;
#pragma unroll
            for (int p = 0; p < 2; p++) {
                const float* rcol = &sm->rs[p][c];
                float rsum, mu_, sig;
                if (ch >= 2) {
                    const float* vcol = &sm->vs[p][ch - 2][c];
                    float rs_ = 0.0f, ms = 0.0f;
#pragma unroll
                    for (int i = 0; i < CI; i++) {
                        const float rv = rcol[i * 32];
                        ms  = fmaf(rv, vcol[i * 32], ms);
                        rs_ += rv;
                    }
                    const float inv = __fdividef(1.0f, rs_ + EPSV);
                    mu_ = ms * inv;
                    float sg = 0.0f;
#pragma unroll
                    for (int i = 0; i < CI; i++) {
                        const float rv = rcol[i * 32];
                        const float d  = vcol[i * 32] - mu_;
                        sg = fmaf(rv * d, d, sg);
                    }
                    sig  = sg * inv + EPSV;
                    rsum = rs_;
                } else {
                    // coord channels: vote constant over i -> closed form
                    float rs_ = 0.0f;
#pragma unroll
                    for (int i = 0; i < CI; i++) rs_ += rcol[i * 32];
                    const float inv = __fdividef(1.0f, rs_ + EPSV);
                    const float vv  = (ch == 0) ? cx[p] : cy[p];
                    mu_  = vv * rs_ * inv;
                    const float d = vv - mu_;
                    sig  = d * d * rs_ * inv + EPSV;
                    rsum = rs_;
                }
                const float hl   = 0.5f * __logf(sig);
                const float i2sv = __fdividef(0.5f, sig);
                sm->mu[p][ch][c] = mu_;
                sm->pa[p][ch][c] = -fmaf(mu_ * mu_, i2sv, hl);
                sm->pb[p][ch][c] = 2.0f * mu_ * i2sv;
                sm->pg[p][ch][c] = -i2sv;
                if (it == 2) sm->cost[p][ch][c] = (beta_v[c * CH + ch] + hl) * rsum;
                if (ch == 0) sm->logit[p][c] = rsum;
            }
        }
        __syncthreads();

        // ---- softmax over c: warp 0 -> p0, warp 1 -> p1 ----
        if (tid < 64) {
            const int p = tid >> 5;
            float t;
            if (it == 2) {
                float cs = 0.0f;
#pragma unroll
                for (int ch = 0; ch < CH; ch++) cs += sm->cost[p][ch][c];
                t = 0.03f * (beta_a[c] - cs);
            } else {
                t = sm->logit[p][c];
            }
            const float mx = warp_max(t);
            const float e  = __expf(t - mx);
            const float se = warp_sum(e);
            sm->ao[p][c] = e / se;
        }
        __syncthreads();
        ao[0] = sm->ao[0][c];
        ao[1] = sm->ao[1][c];
    }

    // ---- write per-position results ----
    if (tid < 64) {
        const int p = tid >> 5;
        g_act[(n0 + p) * CO + c] = sm->ao[p][c];
    }
    for (int k = tid; k < 2 * CO * CH; k += 1024) {
        const int p  = (k >= CO * CH);
        const int kk = k - p * CO * CH;
        g_miu[(n0 + p) * (CO * CH) + kk] = sm->mu[p][kk % CH][kk / CH];
    }
}

// Deterministic spatial mean, two-level: 4 partials per output, fixed order.
// out = [outputs (16*32) | pose_out (16*32*18)]
__global__ void reduce_kernel(float* __restrict__ out)
{
    __shared__ float part[256];
    const int NA = NB * CO;                 // 512
    const int NP = NB * CO * CH;            // 9216
    const int jl = threadIdx.x & 63;
    const int q  = threadIdx.x >> 6;        // 0..3: 16 spatial each
    const int j  = blockIdx.x * 64 + jl;

    float s = 0.0f;
    if (j < NA + NP) {
        const float* src;
        int base, stride;
        if (j < NA) {
            const int b = j >> 5, cc = j & 31;
            src = g_act; base = b * NSPAT * CO + cc; stride = CO;
        } else {
            const int jj = j - NA;
            const int b = jj / (CO * CH), rem = jj % (CO * CH);
            src = g_miu; base = b * NSPAT * (CO * CH) + rem; stride = CO * CH;
        }
#pragma unroll
        for (int sp = q * 16; sp < q * 16 + 16; sp++) s += src[base + sp * stride];
    }
    part[threadIdx.x] = s;
    __syncthreads();
    if (threadIdx.x < 64 && j < NA + NP) {
        const float t = part[jl] + part[jl + 64] + part[jl + 128] + part[jl + 192];
        out[j] = t * (1.0f / NSPAT);
    }
}

extern "C" void kernel_launch(void* const* d_in, const int* in_sizes, int n_in,
                              void* d_out, int out_size)
{
    const float* x      = (const float*)d_in[0];
    const float* w      = (const float*)d_in[1];
    const float* beta_v = (const float*)d_in[2];
    const float* beta_a = (const float*)d_in[3];
    const float* coord  = (const float*)d_in[4];
    float* out = (float*)d_out;

    const size_t smem = sizeof(SM);   // ~163 KB, needs opt-in
    cudaFuncSetAttribute(caps_kernel, cudaFuncAttributeMaxDynamicSharedMemorySize, (int)smem);

    caps_kernel<<<NTOT / 2, 1024, smem>>>(x, w, beta_v, beta_a, coord);

    const int total = NB * CO + NB * CO * CH;          // 9728
    reduce_kernel<<<(total + 63) / 64, 256>>>(out);
}

// round 5
// speedup vs baseline: 3.4758x; 1.4685x over previous
#include <cuda_runtime.h>
#include <math.h>

// Problem constants (fixed by the dataset: B=16, H=W=8, CIN=COUT=32)
#define CI 32
#define CO 32
#define CH 18
#define CHV 16            // vote channels in SMEM (coords handled closed-form)
#define NB 16
#define NSPAT 64
#define NTOT 1024
#define EPSV 1e-9f
#define LN10 2.3025850929940457f

__device__ float g_act[NTOT * CO];            // act_out per (n, c)
__device__ float g_miu[NTOT * CO * CH];       // miu per (n, c, ch)

__device__ __forceinline__ float warp_sum(float v) {
#pragma unroll
    for (int o = 16; o; o >>= 1) v += __shfl_xor_sync(0xffffffffu, v, o);
    return v;
}
__device__ __forceinline__ float warp_max(float v) {
#pragma unroll
    for (int o = 16; o; o >>= 1) v = fmaxf(v, __shfl_xor_sync(0xffffffffu, v, o));
    return v;
}

// ~82 KB -> 2 CTAs/SM
struct SM {
    float  vs[CHV][CI * CO];   // votes [ch-2][i*32+c]
    float  rs[CI * CO];        // c-normalized routing, [i*32+c]
    float  pa[CH][CO];         // lp = pa + v*(pb + pg*v)
    float2 pbg[CH][CO];        // (pb, pg)
    float  mu[CH][CO];
    float  cost[CH][CO];
    float  xs[CI * 17];
    float  logit[CO];
    float  ao[CO];
};

// M-step for one iteration. Units (ch) distributed over 16 warps, lane = c.
// uniform: it0 weights are exactly 1/32 (see theory: ref's it0 weights differ
// from 1/32 by O(eps/act) ~ 1e-9 rel, and its logits are c-independent).
__device__ __forceinline__ void m_step(SM* sm, int c, int wid, float cx, float cy,
                                       bool uniform, bool last,
                                       const float* __restrict__ beta_v)
{
    for (int u = wid; u < CH; u += 16) {
        const int ch = u;
        const float* rcol = &sm->rs[c];
        float rs_, mu_, sig;
        if (ch >= 2) {
            const float* vcol = &sm->vs[ch - 2][c];
            float ms = 0.0f;
            if (uniform) {
                rs_ = 1.0f;
#pragma unroll
                for (int i = 0; i < CI; i++) ms += vcol[i * 32];
                ms *= 0.03125f;
            } else {
                rs_ = 0.0f;
#pragma unroll
                for (int i = 0; i < CI; i++) {
                    const float rv = rcol[i * 32];
                    ms  = fmaf(rv, vcol[i * 32], ms);
                    rs_ += rv;
                }
            }
            const float inv = __fdividef(1.0f, rs_ + EPSV);
            mu_ = ms * inv;
            float sg = 0.0f;
            if (uniform) {
#pragma unroll
                for (int i = 0; i < CI; i++) {
                    const float d = vcol[i * 32] - mu_;
                    sg = fmaf(d, d, sg);
                }
                sg *= 0.03125f;
            } else {
#pragma unroll
                for (int i = 0; i < CI; i++) {
                    const float rv = rcol[i * 32];
                    const float d  = vcol[i * 32] - mu_;
                    sg = fmaf(rv * d, d, sg);
                }
            }
            sig = sg * inv + EPSV;
        } else {
            // coord channels: vote constant over i -> closed form
            if (uniform) {
                rs_ = 1.0f;
            } else {
                rs_ = 0.0f;
#pragma unroll
                for (int i = 0; i < CI; i++) rs_ += rcol[i * 32];
            }
            const float inv = __fdividef(1.0f, rs_ + EPSV);
            const float vv  = (ch == 0) ? cx : cy;
            mu_ = vv * rs_ * inv;
            const float d = vv - mu_;
            sig = d * d * rs_ * inv + EPSV;
        }
        const float hl   = 0.5f * __logf(sig);
        const float i2sv = __fdividef(0.5f, sig);
        sm->mu[ch][c] = mu_;
        if (!last) {
            sm->pa[ch][c]  = -fmaf(mu_ * mu_, i2sv, hl);
            sm->pbg[ch][c] = make_float2(2.0f * mu_ * i2sv, -i2sv);
            if (!uniform && ch == 0) sm->logit[c] = rs_;
        } else {
            sm->cost[ch][c] = (beta_v[c * CH + ch] + hl) * rs_;
        }
    }
}

// One CTA per spatial position n. 512 threads, 16 warps.
// E-step: warp wid handles i = wid and i = wid+16; lane = c.
__global__ void __launch_bounds__(512, 2)
caps_kernel(const float* __restrict__ x,
            const float* __restrict__ w,
            const float* __restrict__ beta_v,
            const float* __restrict__ beta_a,
            const float* __restrict__ coord)
{
    extern __shared__ float smem_raw[];
    SM* sm = reinterpret_cast<SM*>(smem_raw);

    const int tid = threadIdx.x;
    const int c   = tid & 31;
    const int wid = tid >> 5;
    const int n   = blockIdx.x;

    for (int k = tid; k < CI * 17; k += 512) sm->xs[k] = x[n * (CI * 17) + k];
    __syncthreads();

    // --- votes: pose_i (4x4) @ w[i][c] (4x4), for i = wid and wid+16 ---
    float v[2][CHV];
#pragma unroll
    for (int s = 0; s < 2; s++) {
        const int i = wid + 16 * s;
        const float4* wv = reinterpret_cast<const float4*>(w) + (i * CO + c) * 4;
        const float4 w0 = wv[0], w1 = wv[1], w2 = wv[2], w3 = wv[3];
        const float* pr = &sm->xs[i * 17];
#pragma unroll
        for (int a = 0; a < 4; a++) {
            const float p0 = pr[a * 4 + 0], p1 = pr[a * 4 + 1];
            const float p2 = pr[a * 4 + 2], p3 = pr[a * 4 + 3];
            v[s][a * 4 + 0] = p0 * w0.x + p1 * w1.x + p2 * w2.x + p3 * w3.x;
            v[s][a * 4 + 1] = p0 * w0.y + p1 * w1.y + p2 * w2.y + p3 * w3.y;
            v[s][a * 4 + 2] = p0 * w0.z + p1 * w1.z + p2 * w2.z + p3 * w3.z;
            v[s][a * 4 + 3] = p0 * w0.w + p1 * w1.w + p2 * w2.w + p3 * w3.w;
        }
#pragma unroll
        for (int k = 0; k < CHV; k++) sm->vs[k][i * 32 + c] = v[s][k];
    }
    const float act0 = sm->xs[wid * 17 + 16];
    const float act1 = sm->xs[(wid + 16) * 17 + 16];
    const int sp = n & (NSPAT - 1);
    const float cx = coord[2 * sp], cy = coord[2 * sp + 1];
    __syncthreads();                               // vs visible

    // ---- it0: degenerate (uniform weights, uniform softmax) ----
    m_step(sm, c, wid, cx, cy, /*uniform=*/true, /*last=*/false, beta_v);
    __syncthreads();
    float ao_reg = 0.03125f;                       // exact: softmax of equal logits

    // ---- iterations 1 and 2 ----
#pragma unroll
    for (int it = 1; it < 3; it++) {
        const bool last = (it == 2);

        // E-step: both i's share the (ch,c) params
        float S0 = 0.0f, m0 = -1e30f, S1 = 0.0f, m1 = -1e30f;
#pragma unroll
        for (int ch = 0; ch < CH; ch++) {
            const float  pav = sm->pa[ch][c];
            const float2 bg  = sm->pbg[ch][c];
            const float vv0 = (ch == 0) ? cx : (ch == 1) ? cy : v[0][ch - 2];
            const float vv1 = (ch == 0) ? cx : (ch == 1) ? cy : v[1][ch - 2];
            const float l0 = fmaf(fmaf(bg.y, vv0, bg.x), vv0, pav);
            const float l1 = fmaf(fmaf(bg.y, vv1, bg.x), vv1, pav);
            S0 += l0; m0 = fmaxf(m0, l0);
            S1 += l1; m1 = fmaxf(m1, l1);
        }
        const float M0 = warp_max(m0);
        const float M1 = warp_max(m1);
        const float pv0 = __expf(S0 - 18.0f * M0 + 18.0f * LN10);
        const float pv1 = __expf(S1 - 18.0f * M1 + 18.0f * LN10);
        const float ap0 = pv0 * ao_reg;
        const float ap1 = pv1 * ao_reg;
        const float sa0 = warp_sum(ap0);
        const float sa1 = warp_sum(ap1);
        const float rv0 = (ap0 / (sa0 + EPSV)) * act0;
        const float rv1 = (ap1 / (sa1 + EPSV)) * act1;
        const float t0 = warp_sum(rv0);
        const float t1 = warp_sum(rv1);
        sm->rs[wid * 32 + c]        = rv0 / (t0 + EPSV);
        sm->rs[(wid + 16) * 32 + c] = rv1 / (t1 + EPSV);
        __syncthreads();

        m_step(sm, c, wid, cx, cy, /*uniform=*/false, last, beta_v);
        __syncthreads();

        // softmax over c (warp 0); overlap g_miu writes on last iter
        if (tid < 32) {
            float t;
            if (last) {
                float cs = 0.0f;
#pragma unroll
                for (int ch = 0; ch < CH; ch++) cs += sm->cost[ch][c];
                t = 0.03f * (beta_a[c] - cs);
            } else {
                t = sm->logit[c];
            }
            const float mx = warp_max(t);
            const float e  = __expf(t - mx);
            const float se = warp_sum(e);
            sm->ao[c] = e / se;
        }
        if (last) {
            for (int k = tid; k < CO * CH; k += 512) {
                const int cc = k / CH, ch = k - cc * CH;
                g_miu[n * (CO * CH) + k] = sm->mu[ch][cc];
            }
        }
        __syncthreads();
        ao_reg = sm->ao[c];
    }

    if (tid < 32) g_act[n * CO + c] = sm->ao[c];
}

// Deterministic spatial mean, two-level: 4 partials per output, fixed order.
__global__ void reduce_kernel(float* __restrict__ out)
{
    __shared__ float part[256];
    const int NA = NB * CO;                 // 512
    const int NP = NB * CO * CH;            // 9216
    const int jl = threadIdx.x & 63;
    const int q  = threadIdx.x >> 6;        // 0..3: 16 spatial each
    const int j  = blockIdx.x * 64 + jl;

    float s = 0.0f;
    if (j < NA + NP) {
        const float* src;
        int base, stride;
        if (j < NA) {
            const int b = j >> 5, cc = j & 31;
            src = g_act; base = b * NSPAT * CO + cc; stride = CO;
        } else {
            const int jj = j - NA;
            const int b = jj / (CO * CH), rem = jj % (CO * CH);
            src = g_miu; base = b * NSPAT * (CO * CH) + rem; stride = CO * CH;
        }
#pragma unroll
        for (int sp = q * 16; sp < q * 16 + 16; sp++) s += src[base + sp * stride];
    }
    part[threadIdx.x] = s;
    __syncthreads();
    if (threadIdx.x < 64 && j < NA + NP) {
        const float t = part[jl] + part[jl + 64] + part[jl + 128] + part[jl + 192];
        out[j] = t * (1.0f / NSPAT);
    }
}

extern "C" void kernel_launch(void* const* d_in, const int* in_sizes, int n_in,
                              void* d_out, int out_size)
{
    const float* x      = (const float*)d_in[0];
    const float* w      = (const float*)d_in[1];
    const float* beta_v = (const float*)d_in[2];
    const float* beta_a = (const float*)d_in[3];
    const float* coord  = (const float*)d_in[4];
    float* out = (float*)d_out;

    const size_t smem = sizeof(SM);        // ~82 KB -> 2 CTAs/SM
    cudaFuncSetAttribute(caps_kernel, cudaFuncAttributeMaxDynamicSharedMemorySize, (int)smem);

    caps_kernel<<<NTOT, 512, smem>>>(x, w, beta_v, beta_a, coord);

    const int total = NB * CO + NB * CO * CH;   // 9728
    reduce_kernel<<<(total + 63) / 64, 256>>>(out);
}

// round 6
// speedup vs baseline: 4.4175x; 1.2709x over previous
#include <cuda_runtime.h>
#include <math.h>

// Problem constants (fixed by the dataset: B=16, H=W=8, CIN=COUT=32)
#define CI 32
#define CO 32
#define CH 18
#define CHV 16            // vote channels in SMEM (coords handled closed-form)
#define NB 16
#define NSPAT 64
#define NTOT 1024
#define EPSV 1e-9f
#define LN10 2.3025850929940457f

__device__ float g_act[NTOT * CO];            // act_out per (n, c)
__device__ float g_miu[NTOT * CO * CH];       // miu per (n, c, ch)

__device__ __forceinline__ float warp_sum(float v) {
#pragma unroll
    for (int o = 16; o; o >>= 1) v += __shfl_xor_sync(0xffffffffu, v, o);
    return v;
}
__device__ __forceinline__ float warp_max(float v) {
#pragma unroll
    for (int o = 16; o; o >>= 1) v = fmaxf(v, __shfl_xor_sync(0xffffffffu, v, o));
    return v;
}

// ~82 KB -> 2 CTAs/SM
struct SM {
    float  vs[CHV][CI * CO];   // votes [ch-2][i*32+c]
    float  rs[CI * CO];        // c-normalized routing, [i*32+c]
    float  pa[CH][CO];         // lp = pa + v*(pb + pg*v)
    float2 pbg[CH][CO];        // (pb, pg)
    float  mu[CH][CO];
    float  cost[CH][CO];
    float  xs[CI * 17];
    float  logit[CO];
    float  ao[CO];
};

// M-step, one-pass moments. Units (ch) over 16 warps, lane = c.
// sigma = T2/T0 - mu^2 (one pass); fmaxf guards rounding-negative. Differs
// from ref's two-pass by ~1e-6 rel — far inside the 1e-3 gate.
__device__ __forceinline__ void m_step(SM* sm, int c, int wid, float cx, float cy,
                                       bool uniform, bool last,
                                       const float* __restrict__ beta_v)
{
    for (int u = wid; u < CH; u += 16) {
        const int ch = u;
        const float* rcol = &sm->rs[c];
        float rs_, mu_, sig;
        if (ch >= 2) {
            const float* vcol = &sm->vs[ch - 2][c];
            float T1 = 0.0f, T2 = 0.0f;
            if (uniform) {
#pragma unroll
                for (int i = 0; i < CI; i++) {
                    const float vv = vcol[i * 32];
                    T1 += vv;
                    T2 = fmaf(vv, vv, T2);
                }
                rs_ = 1.0f;
                mu_ = T1 * 0.03125f;
                sig = fmaxf(fmaf(-mu_, mu_, T2 * 0.03125f), 0.0f) + EPSV;
            } else {
                float T0 = 0.0f;
#pragma unroll
                for (int i = 0; i < CI; i++) {
                    const float rv = rcol[i * 32];
                    const float vv = vcol[i * 32];
                    T0 += rv;
                    T1 = fmaf(rv, vv, T1);
                    T2 = fmaf(rv * vv, vv, T2);
                }
                const float inv = __fdividef(1.0f, T0 + EPSV);
                rs_ = T0;
                mu_ = T1 * inv;
                sig = fmaxf(fmaf(-mu_, mu_, T2 * inv), 0.0f) + EPSV;
            }
        } else {
            // coord channels: vote constant over i -> closed form
            if (uniform) {
                rs_ = 1.0f;
            } else {
                rs_ = 0.0f;
#pragma unroll
                for (int i = 0; i < CI; i++) rs_ += rcol[i * 32];
            }
            const float inv = __fdividef(1.0f, rs_ + EPSV);
            const float vv  = (ch == 0) ? cx : cy;
            mu_ = vv * rs_ * inv;
            const float d = vv - mu_;
            sig = d * d * rs_ * inv + EPSV;
        }
        const float hl   = 0.5f * __logf(sig);
        const float i2sv = __fdividef(0.5f, sig);
        sm->mu[ch][c] = mu_;
        if (!last) {
            sm->pa[ch][c]  = -fmaf(mu_ * mu_, i2sv, hl);
            sm->pbg[ch][c] = make_float2(2.0f * mu_ * i2sv, -i2sv);
            if (!uniform && ch == 0) sm->logit[c] = rs_;
        } else {
            sm->cost[ch][c] = (beta_v[c * CH + ch] + hl) * rs_;
        }
    }
}

// One CTA per spatial position n. 512 threads, 16 warps.
// E-step: warp wid handles i = wid and i = wid+16; lane = c.
__global__ void __launch_bounds__(512, 2)
caps_kernel(const float* __restrict__ x,
            const float* __restrict__ w,
            const float* __restrict__ beta_v,
            const float* __restrict__ beta_a,
            const float* __restrict__ coord)
{
    extern __shared__ float smem_raw[];
    SM* sm = reinterpret_cast<SM*>(smem_raw);

    const int tid = threadIdx.x;
    const int c   = tid & 31;
    const int wid = tid >> 5;
    const int n   = blockIdx.x;

    for (int k = tid; k < CI * 17; k += 512) sm->xs[k] = x[n * (CI * 17) + k];
    __syncthreads();

    // --- votes: pose_i (4x4) @ w[i][c] (4x4), for i = wid and wid+16 ---
    float v[2][CHV];
#pragma unroll
    for (int s = 0; s < 2; s++) {
        const int i = wid + 16 * s;
        const float4* wv = reinterpret_cast<const float4*>(w) + (i * CO + c) * 4;
        const float4 w0 = wv[0], w1 = wv[1], w2 = wv[2], w3 = wv[3];
        const float* pr = &sm->xs[i * 17];
#pragma unroll
        for (int a = 0; a < 4; a++) {
            const float p0 = pr[a * 4 + 0], p1 = pr[a * 4 + 1];
            const float p2 = pr[a * 4 + 2], p3 = pr[a * 4 + 3];
            v[s][a * 4 + 0] = p0 * w0.x + p1 * w1.x + p2 * w2.x + p3 * w3.x;
            v[s][a * 4 + 1] = p0 * w0.y + p1 * w1.y + p2 * w2.y + p3 * w3.y;
            v[s][a * 4 + 2] = p0 * w0.z + p1 * w1.z + p2 * w2.z + p3 * w3.z;
            v[s][a * 4 + 3] = p0 * w0.w + p1 * w1.w + p2 * w2.w + p3 * w3.w;
        }
#pragma unroll
        for (int k = 0; k < CHV; k++) sm->vs[k][i * 32 + c] = v[s][k];
    }
    const float act0 = sm->xs[wid * 17 + 16];
    const float act1 = sm->xs[(wid + 16) * 17 + 16];
    const int sp = n & (NSPAT - 1);
    const float cx = coord[2 * sp], cy = coord[2 * sp + 1];
    __syncthreads();                               // vs visible

    // ---- it0: degenerate (uniform weights, uniform softmax) ----
    m_step(sm, c, wid, cx, cy, /*uniform=*/true, /*last=*/false, beta_v);
    __syncthreads();
    float ao_reg = 0.03125f;                       // exact: softmax of equal logits

    // ---- iterations 1 and 2 ----
#pragma unroll
    for (int it = 1; it < 3; it++) {
        const bool last = (it == 2);

        // E-step: both i's share the (ch,c) params
        float S0 = 0.0f, m0 = -1e30f, S1 = 0.0f, m1 = -1e30f;
#pragma unroll
        for (int ch = 0; ch < CH; ch++) {
            const float  pav = sm->pa[ch][c];
            const float2 bg  = sm->pbg[ch][c];
            const float vv0 = (ch == 0) ? cx : (ch == 1) ? cy : v[0][ch - 2];
            const float vv1 = (ch == 0) ? cx : (ch == 1) ? cy : v[1][ch - 2];
            const float l0 = fmaf(fmaf(bg.y, vv0, bg.x), vv0, pav);
            const float l1 = fmaf(fmaf(bg.y, vv1, bg.x), vv1, pav);
            S0 += l0; m0 = fmaxf(m0, l0);
            S1 += l1; m1 = fmaxf(m1, l1);
        }
        const float M0 = warp_max(m0);
        const float M1 = warp_max(m1);
        const float pv0 = __expf(S0 - 18.0f * M0 + 18.0f * LN10);
        const float pv1 = __expf(S1 - 18.0f * M1 + 18.0f * LN10);
        const float ap0 = pv0 * ao_reg;
        const float ap1 = pv1 * ao_reg;
        const float sa0 = warp_sum(ap0);
        const float sa1 = warp_sum(ap1);
        // Σ_c (ap/(sa+EPS)·act) = act·sa/(sa+EPS): act const over c -> no shuffle
        const float rv0 = (ap0 / (sa0 + EPSV)) * act0;
        const float rv1 = (ap1 / (sa1 + EPSV)) * act1;
        const float t0  = act0 * (sa0 / (sa0 + EPSV));
        const float t1  = act1 * (sa1 / (sa1 + EPSV));
        sm->rs[wid * 32 + c]        = rv0 / (t0 + EPSV);
        sm->rs[(wid + 16) * 32 + c] = rv1 / (t1 + EPSV);
        __syncthreads();

        m_step(sm, c, wid, cx, cy, /*uniform=*/false, last, beta_v);
        __syncthreads();

        // softmax over c (warp 0); overlap g_miu writes on last iter
        if (tid < 32) {
            float t;
            if (last) {
                float cs = 0.0f;
#pragma unroll
                for (int ch = 0; ch < CH; ch++) cs += sm->cost[ch][c];
                t = 0.03f * (beta_a[c] - cs);
            } else {
                t = sm->logit[c];
            }
            const float mx = warp_max(t);
            const float e  = __expf(t - mx);
            const float se = warp_sum(e);
            sm->ao[c] = e / se;
        }
        if (last) {
            for (int k = tid; k < CO * CH; k += 512) {
                const int cc = k / CH, ch = k - cc * CH;
                g_miu[n * (CO * CH) + k] = sm->mu[ch][cc];
            }
        }
        __syncthreads();
        ao_reg = sm->ao[c];
    }

    if (tid < 32) g_act[n * CO + c] = sm->ao[c];
}

// Deterministic spatial mean, two-level: 4 partials per output, fixed order.
__global__ void reduce_kernel(float* __restrict__ out)
{
    __shared__ float part[256];
    const int NA = NB * CO;                 // 512
    const int NP = NB * CO * CH;            // 9216
    const int jl = threadIdx.x & 63;
    const int q  = threadIdx.x >> 6;        // 0..3: 16 spatial each
    const int j  = blockIdx.x * 64 + jl;

    float s = 0.0f;
    if (j < NA + NP) {
        const float* src;
        int base, stride;
        if (j < NA) {
            const int b = j >> 5, cc = j & 31;
            src = g_act; base = b * NSPAT * CO + cc; stride = CO;
        } else {
            const int jj = j - NA;
            const int b = jj / (CO * CH), rem = jj % (CO * CH);
            src = g_miu; base = b * NSPAT * (CO * CH) + rem; stride = CO * CH;
        }
#pragma unroll
        for (int sp = q * 16; sp < q * 16 + 16; sp++) s += src[base + sp * stride];
    }
    part[threadIdx.x] = s;
    __syncthreads();
    if (threadIdx.x < 64 && j < NA + NP) {
        const float t = part[jl] + part[jl + 64] + part[jl + 128] + part[jl + 192];
        out[j] = t * (1.0f / NSPAT);
    }
}

extern "C" void kernel_launch(void* const* d_in, const int* in_sizes, int n_in,
                              void* d_out, int out_size)
{
    const float* x      = (const float*)d_in[0];
    const float* w      = (const float*)d_in[1];
    const float* beta_v = (const float*)d_in[2];
    const float* beta_a = (const float*)d_in[3];
    const float* coord  = (const float*)d_in[4];
    float* out = (float*)d_out;

    const size_t smem = sizeof(SM);        // ~82 KB -> 2 CTAs/SM
    cudaFuncSetAttribute(caps_kernel, cudaFuncAttributeMaxDynamicSharedMemorySize, (int)smem);

    caps_kernel<<<NTOT, 512, smem>>>(x, w, beta_v, beta_a, coord);

    const int total = NB * CO + NB * CO * CH;   // 9728
    reduce_kernel<<<(total + 63) / 64, 256>>>(out);
}

// round 7
// speedup vs baseline: 4.4614x; 1.0100x over previous
#include <cuda_runtime.h>
#include <math.h>

// Problem constants (fixed by the dataset: B=16, H=W=8, CIN=COUT=32)
#define CI 32
#define CO 32
#define CH 18
#define CHV 16            // vote channels in SMEM (coords handled closed-form)
#define NB 16
#define NSPAT 64
#define NTOT 1024
#define EPSV 1e-9f
#define LN10 2.3025850929940457f

__device__ float g_act[NTOT * CO];            // act_out per (n, c)
__device__ float g_miu[NTOT * CO * CH];       // miu per (n, c, ch)

__device__ __forceinline__ float warp_sum(float v) {
#pragma unroll
    for (int o = 16; o; o >>= 1) v += __shfl_xor_sync(0xffffffffu, v, o);
    return v;
}
__device__ __forceinline__ float warp_max(float v) {
#pragma unroll
    for (int o = 16; o; o >>= 1) v = fmaxf(v, __shfl_xor_sync(0xffffffffu, v, o));
    return v;
}

// 75 KB. Lifetime unions: xs (pre-vote) aliases rs (post-it0);
// pa (read up to it2-E) aliases cost (written it2-M, read at the end).
struct SM {
    float  vs[CHV][CI * CO];     // votes [ch-2][i*32+c]          (64 KB)
    union {
        float xs[CI * 17];       // raw x row, dead after votes
        float rs[CI * CO];       // c-normalized routing [i*32+c]
    } u;
    union {
        float pa[CH][CO];        // lp = pa + v*(pb + pg*v); dead after it2-E
        float cost[CH][CO];      // written it2-M, read by final softmax
    } q;
    float2 pbg[CH][CO];          // (pb, pg)
    float  logit[CO];
    float  ao[CO];               // (kept for alignment/debug; unused hot path)
};

// M-step, one-pass moments. Units (ch) over 16 warps, lane = c.
template<bool UNIFORM, bool LAST>
__device__ __forceinline__ void m_step(SM* sm, int c, int wid, float cx, float cy,
                                       int n, const float* __restrict__ beta_v)
{
    for (int u = wid; u < CH; u += 16) {
        const int ch = u;
        const float* rcol = &sm->u.rs[c];
        float rs_, mu_, sig;
        if (ch >= 2) {
            const float* vcol = &sm->vs[ch - 2][c];
            float T1 = 0.0f, T2 = 0.0f;
            if (UNIFORM) {
#pragma unroll
                for (int i = 0; i < CI; i++) {
                    const float vv = vcol[i * 32];
                    T1 += vv;
                    T2 = fmaf(vv, vv, T2);
                }
                rs_ = 1.0f;
                mu_ = T1 * 0.03125f;
                sig = fmaxf(fmaf(-mu_, mu_, T2 * 0.03125f), 0.0f) + EPSV;
            } else {
                float T0 = 0.0f;
#pragma unroll
                for (int i = 0; i < CI; i++) {
                    const float rv = rcol[i * 32];
                    const float vv = vcol[i * 32];
                    T0 += rv;
                    T1 = fmaf(rv, vv, T1);
                    T2 = fmaf(rv * vv, vv, T2);
                }
                const float inv = __fdividef(1.0f, T0 + EPSV);
                rs_ = T0;
                mu_ = T1 * inv;
                sig = fmaxf(fmaf(-mu_, mu_, T2 * inv), 0.0f) + EPSV;
            }
        } else {
            // coord channels: vote constant over i -> closed form
            if (UNIFORM) {
                rs_ = 1.0f;
            } else {
                rs_ = 0.0f;
#pragma unroll
                for (int i = 0; i < CI; i++) rs_ += rcol[i * 32];
            }
            const float inv = __fdividef(1.0f, rs_ + EPSV);
            const float vv  = (ch == 0) ? cx : cy;
            mu_ = vv * rs_ * inv;
            const float d = vv - mu_;
            sig = d * d * rs_ * inv + EPSV;
        }
        const float hl   = 0.5f * __logf(sig);
        const float i2sv = __fdividef(0.5f, sig);
        if (!LAST) {
            sm->q.pa[ch][c] = -fmaf(mu_ * mu_, i2sv, hl);
            sm->pbg[ch][c]  = make_float2(2.0f * mu_ * i2sv, -i2sv);
            if (!UNIFORM && ch == 0) sm->logit[c] = rs_;
        } else {
            g_miu[n * (CO * CH) + c * CH + ch] = mu_;     // direct output write
            sm->q.cost[ch][c] = (beta_v[c * CH + ch] + hl) * rs_;
        }
    }
}

// E-step for one iteration (warp wid = i-pair {wid, wid+16}, lane = c).
__device__ __forceinline__ void e_step(SM* sm, const float v[2][CHV],
                                       int c, int wid,
                                       float cx, float cy,
                                       float act0, float act1, float ao_reg)
{
    float S0 = 0.0f, m0 = -1e30f, S1 = 0.0f, m1 = -1e30f;
#pragma unroll
    for (int ch = 0; ch < CH; ch++) {
        const float  pav = sm->q.pa[ch][c];
        const float2 bg  = sm->pbg[ch][c];
        const float vv0 = (ch == 0) ? cx : (ch == 1) ? cy : v[0][ch - 2];
        const float vv1 = (ch == 0) ? cx : (ch == 1) ? cy : v[1][ch - 2];
        const float l0 = fmaf(fmaf(bg.y, vv0, bg.x), vv0, pav);
        const float l1 = fmaf(fmaf(bg.y, vv1, bg.x), vv1, pav);
        S0 += l0; m0 = fmaxf(m0, l0);
        S1 += l1; m1 = fmaxf(m1, l1);
    }
    const float M0 = warp_max(m0);
    const float M1 = warp_max(m1);
    const float pv0 = __expf(S0 - 18.0f * M0 + 18.0f * LN10);
    const float pv1 = __expf(S1 - 18.0f * M1 + 18.0f * LN10);
    const float ap0 = pv0 * ao_reg;
    const float ap1 = pv1 * ao_reg;
    const float sa0 = warp_sum(ap0);
    const float sa1 = warp_sum(ap1);
    // Σ_c(ap/(sa+EPS)·act) = act·sa/(sa+EPS): act const over c -> no shuffle
    const float rv0 = (ap0 / (sa0 + EPSV)) * act0;
    const float rv1 = (ap1 / (sa1 + EPSV)) * act1;
    const float t0  = act0 * (sa0 / (sa0 + EPSV));
    const float t1  = act1 * (sa1 / (sa1 + EPSV));
    sm->u.rs[wid * 32 + c]        = rv0 / (t0 + EPSV);
    sm->u.rs[(wid + 16) * 32 + c] = rv1 / (t1 + EPSV);
}

// One CTA per spatial position n. 512 threads, 16 warps. 7 barriers total.
__global__ void __launch_bounds__(512, 2)
caps_kernel(const float* __restrict__ x,
            const float* __restrict__ w,
            const float* __restrict__ beta_v,
            const float* __restrict__ beta_a,
            const float* __restrict__ coord)
{
    extern __shared__ float smem_raw[];
    SM* sm = reinterpret_cast<SM*>(smem_raw);

    const int tid = threadIdx.x;
    const int c   = tid & 31;
    const int wid = tid >> 5;
    const int n   = blockIdx.x;

    for (int k = tid; k < CI * 17; k += 512) sm->u.xs[k] = x[n * (CI * 17) + k];
    __syncthreads();                                         // B1

    // --- votes: pose_i (4x4) @ w[i][c] (4x4), for i = wid and wid+16 ---
    float v[2][CHV];
#pragma unroll
    for (int s = 0; s < 2; s++) {
        const int i = wid + 16 * s;
        const float4* wv = reinterpret_cast<const float4*>(w) + (i * CO + c) * 4;
        const float4 w0 = wv[0], w1 = wv[1], w2 = wv[2], w3 = wv[3];
        const float* pr = &sm->u.xs[i * 17];
#pragma unroll
        for (int a = 0; a < 4; a++) {
            const float p0 = pr[a * 4 + 0], p1 = pr[a * 4 + 1];
            const float p2 = pr[a * 4 + 2], p3 = pr[a * 4 + 3];
            v[s][a * 4 + 0] = p0 * w0.x + p1 * w1.x + p2 * w2.x + p3 * w3.x;
            v[s][a * 4 + 1] = p0 * w0.y + p1 * w1.y + p2 * w2.y + p3 * w3.y;
            v[s][a * 4 + 2] = p0 * w0.z + p1 * w1.z + p2 * w2.z + p3 * w3.z;
            v[s][a * 4 + 3] = p0 * w0.w + p1 * w1.w + p2 * w2.w + p3 * w3.w;
        }
#pragma unroll
        for (int k = 0; k < CHV; k++) sm->vs[k][i * 32 + c] = v[s][k];
    }
    const float act0 = sm->u.xs[wid * 17 + 16];
    const float act1 = sm->u.xs[(wid + 16) * 17 + 16];
    const int sp = n & (NSPAT - 1);
    const float cx = coord[2 * sp], cy = coord[2 * sp + 1];
    __syncthreads();                                         // B2 (vs ready; xs dead)

    // ---- it0: uniform weights; softmax of equal logits is exactly 1/32 ----
    m_step<true, false>(sm, c, wid, cx, cy, n, beta_v);
    __syncthreads();                                         // B3

    // ---- it1: ao = 1/32 (constant, no softmax phase) ----
    e_step(sm, v, c, wid, cx, cy, act0, act1, 0.03125f);
    __syncthreads();                                         // B4
    m_step<false, false>(sm, c, wid, cx, cy, n, beta_v);
    __syncthreads();                                         // B5

    // ---- it2: softmax(logit) inlined per-warp (no separate phase) ----
    float ao_reg;
    {
        const float t  = sm->logit[c];
        const float mx = warp_max(t);
        const float e  = __expf(t - mx);
        const float se = warp_sum(e);
        ao_reg = e / se;
    }
    e_step(sm, v, c, wid, cx, cy, act0, act1, ao_reg);
    __syncthreads();                                         // B6
    m_step<false, true>(sm, c, wid, cx, cy, n, beta_v);      // writes g_miu + cost
    __syncthreads();                                         // B7

    // final activation softmax: warp 0 only; other warps exit
    if (tid < 32) {
        float cs = 0.0f;
#pragma unroll
        for (int ch = 0; ch < CH; ch++) cs += sm->q.cost[ch][c];
        const float t  = 0.03f * (beta_a[c] - cs);
        const float mx = warp_max(t);
        const float e  = __expf(t - mx);
        const float se = warp_sum(e);
        g_act[n * CO + c] = e / se;
    }
}

// Deterministic spatial mean, two-level: 4 partials per output, fixed order.
__global__ void reduce_kernel(float* __restrict__ out)
{
    __shared__ float part[256];
    const int NA = NB * CO;                 // 512
    const int NP = NB * CO * CH;            // 9216
    const int jl = threadIdx.x & 63;
    const int q  = threadIdx.x >> 6;        // 0..3: 16 spatial each
    const int j  = blockIdx.x * 64 + jl;

    float s = 0.0f;
    if (j < NA + NP) {
        const float* src;
        int base, stride;
        if (j < NA) {
            const int b = j >> 5, cc = j & 31;
            src = g_act; base = b * NSPAT * CO + cc; stride = CO;
        } else {
            const int jj = j - NA;
            const int b = jj / (CO * CH), rem = jj % (CO * CH);
            src = g_miu; base = b * NSPAT * (CO * CH) + rem; stride = CO * CH;
        }
#pragma unroll
        for (int sp = q * 16; sp < q * 16 + 16; sp++) s += src[base + sp * stride];
    }
    part[threadIdx.x] = s;
    __syncthreads();
    if (threadIdx.x < 64 && j < NA + NP) {
        const float t = part[jl] + part[jl + 64] + part[jl + 128] + part[jl + 192];
        out[j] = t * (1.0f / NSPAT);
    }
}

extern "C" void kernel_launch(void* const* d_in, const int* in_sizes, int n_in,
                              void* d_out, int out_size)
{
    const float* x      = (const float*)d_in[0];
    const float* w      = (const float*)d_in[1];
    const float* beta_v = (const float*)d_in[2];
    const float* beta_a = (const float*)d_in[3];
    const float* coord  = (const float*)d_in[4];
    float* out = (float*)d_out;

    const size_t smem = sizeof(SM);        // 75 KB -> 2 CTAs/SM
    cudaFuncSetAttribute(caps_kernel, cudaFuncAttributeMaxDynamicSharedMemorySize, (int)smem);

    caps_kernel<<<NTOT, 512, smem>>>(x, w, beta_v, beta_a, coord);

    const int total = NB * CO + NB * CO * CH;   // 9728
    reduce_kernel<<<(total + 63) / 64, 256>>>(out);
}